// round 8
// baseline (speedup 1.0000x reference)
#include <cuda_runtime.h>
#include <cstdint>
#include <cstddef>

// ---------------------------------------------------------------------------
// SwinSelfAttention fused kernel v4 (resubmit — R7 bench was an infra failure)
//   fp32 + packed f32x2 FFMA. 256 threads/CTA, 2 CTAs per SM (two windows
//   co-resident -> phase overlap: one CTA's LDS-heavy attention hides under
//   the other's FMA-heavy projection GEMM).
//   B=16, NW=256, S=64, D=256, H=8, HD=32. One block per window.
//   SMEM 112640 B/CTA: bias table -> registers, At folded into Ls (in-place
//   transpose), X transpose staged through a 16-row chunk buffer.
// ---------------------------------------------------------------------------

namespace {
constexpr int Dc = 256;
constexpr int Hc = 8;
constexpr int NWc = 256;
constexpr int THREADS = 256;
constexpr float QSCALE = 0.17677669529663688f;  // 1/sqrt(32)

constexpr int XT_STRIDE = 68;   // Xt[k=256][68]: cols 0..31 = m0..31, 36..67 = m32..63
constexpr int XC_STRIDE = 257;  // chunk staging [16][257]
constexpr int WS_STRIDE = 98;   // Ws[k=64][98] (96 rows used: q|k|v x32 of one head)
constexpr int QK_STRIDE = 68;
constexpr int LS_STRIDE = 68;

constexpr int OFF_XT = 0;                          // 17408 floats
constexpr int OFF_U  = OFF_XT + 256 * XT_STRIDE;   // union base
// union members (all phase-disjoint, guarded by __syncthreads):
//   Xchunk [16][257] = 4112   (startup transpose staging)
//   Ws     [64][98]  = 6272   (per GEMM0 k-tile stage)
//   attn:  Qt 2176 | Kt 2176 | Vh 2048 | Ls 4352  = 10752
constexpr int OFF_WS = OFF_U;
constexpr int OFF_XC = OFF_U;
constexpr int OFF_QT = OFF_U;
constexpr int OFF_KT = OFF_QT + 32 * QK_STRIDE;    // +2176
constexpr int OFF_VH = OFF_KT + 32 * QK_STRIDE;    // +2176
constexpr int OFF_LS = OFF_VH + 64 * 32;           // +2048
constexpr int UNION_FLOATS = 2176 + 2176 + 2048 + 64 * LS_STRIDE;  // 10752
constexpr int SMEM_FLOATS = 256 * XT_STRIDE + UNION_FLOATS;        // 28160 = 112640 B
static_assert(UNION_FLOATS >= 64 * WS_STRIDE, "Ws fits union");
static_assert(UNION_FLOATS >= 16 * XC_STRIDE, "Xchunk fits union");
static_assert(2 * SMEM_FLOATS * 4 <= 233472, "two CTAs per SM");

using ull = unsigned long long;
}  // namespace

__device__ __forceinline__ void ffma2(ull& d, ull a, ull b) {
    asm("fma.rn.f32x2 %0, %1, %2, %0;" : "+l"(d) : "l"(a), "l"(b));
}
__device__ __forceinline__ ull pack2(float x) {
    ull r; unsigned u = __float_as_uint(x);
    asm("mov.b64 %0, {%1, %1};" : "=l"(r) : "r"(u));
    return r;
}
__device__ __forceinline__ float2 unpack2(ull v) {
    unsigned lo, hi;
    asm("mov.b64 {%0, %1}, %2;" : "=r"(lo), "=r"(hi) : "l"(v));
    return make_float2(__uint_as_float(lo), __uint_as_float(hi));
}

__global__ void __launch_bounds__(THREADS, 2)
swin_attn_kernel(const float* __restrict__ patches,
                 const float* __restrict__ wq, const float* __restrict__ bq,
                 const float* __restrict__ wk, const float* __restrict__ bk,
                 const float* __restrict__ wv, const float* __restrict__ bvp,
                 const float* __restrict__ pos_bias,
                 const unsigned char* __restrict__ mask,
                 float* __restrict__ out) {
    extern __shared__ float sm[];
    float* Xt = sm + OFF_XT;
    float* Xc = sm + OFF_XC;
    float* Ws = sm + OFF_WS;
    float* Qt = sm + OFF_QT;
    float* Kt = sm + OFF_KT;
    float* Vh = sm + OFF_VH;
    float* Ls = sm + OFF_LS;

    const int tid = threadIdx.x;
    const int bw  = blockIdx.x;
    const int nw  = bw & (NWc - 1);
    const float* Xg = patches + (size_t)bw * (64 * Dc);
    float* Og = out + (size_t)bw * (64 * Dc);
    const float NEG_INF = __int_as_float(0xff800000);

    // ---- attention thread mapping (fixed for the whole kernel) ----
    const int q0a = (tid & 15) * 4;   // GEMM1/GEMM2 q base
    const int k0a = (tid >> 4) * 4;   // GEMM1 k base
    // per-thread relative-position bias tile (head-invariant) -> registers
    float bias_r[4][4];
    #pragma unroll
    for (int i = 0; i < 4; ++i)
        #pragma unroll
        for (int j = 0; j < 4; ++j) {
            int q = q0a + i, k = k0a + j;
            int ri = (q >> 3) - (k >> 3) + 7;
            int rj = (q & 7)  - (k & 7)  + 7;
            bias_r[i][j] = pos_bias[ri * 15 + rj];
        }

    // ---- X transpose: global -> Xc chunks -> Xt[k][mcol] ----
    #pragma unroll
    for (int c = 0; c < 4; ++c) {
        __syncthreads();  // prior chunk's Xc reads done (no-op for c=0)
        #pragma unroll
        for (int i = 0; i < 4; ++i) {
            int f4 = tid + i * THREADS;        // 0..1023
            int ml = f4 >> 6, k4 = f4 & 63;
            float4 v = *reinterpret_cast<const float4*>(
                Xg + (c * 16 + ml) * Dc + k4 * 4);
            float* d = Xc + ml * XC_STRIDE + k4 * 4;
            d[0] = v.x; d[1] = v.y; d[2] = v.z; d[3] = v.w;
        }
        __syncthreads();
        const int k = tid;                     // 0..255
        const int mcolb = c * 16 + (c >= 2 ? 4 : 0);
        const float* s = Xc + k;
        float* d = Xt + k * XT_STRIDE + mcolb;
        #pragma unroll
        for (int j = 0; j < 4; ++j) {
            float4 v;
            v.x = s[(4 * j + 0) * XC_STRIDE];
            v.y = s[(4 * j + 1) * XC_STRIDE];
            v.z = s[(4 * j + 2) * XC_STRIDE];
            v.w = s[(4 * j + 3) * XC_STRIDE];
            *reinterpret_cast<float4*>(d + 4 * j) = v;
        }
    }
    // kt-loop's first sync orders last chunk reads + Xt writes.

    const int tm8   = (tid & 7) * 8;                 // GEMM0 m base
    const int tmcol = tm8 + (tm8 >= 32 ? 4 : 0);     // shifted Xt column
    const int tn3   = (tid >> 3) * 3;                // GEMM0 col base (0..93)

    for (int h = 0; h < Hc; ++h) {
        // ============ GEMM0: [Q|K|V]_h = X @ Wcat_h^T  (64 x 96) ============
        ull acc2[4][3];
        #pragma unroll
        for (int i = 0; i < 4; ++i)
            #pragma unroll
            for (int j = 0; j < 3; ++j) acc2[i][j] = 0ull;

        for (int kt = 0; kt < 4; ++kt) {
            const int k0 = kt * 64;
            __syncthreads();  // prior union consumers done
            #pragma unroll
            for (int i = 0; i < 6; ++i) {
                int f4 = tid + i * THREADS;    // 0..1535
                int row = f4 >> 4;             // 0..95
                int k4  = f4 & 15;
                const float* src;
                if (row < 32)      src = wq + (h * 32 + row) * Dc;
                else if (row < 64) src = wk + (h * 32 + row - 32) * Dc;
                else               src = wv + (h * 32 + row - 64) * Dc;
                float4 v = *reinterpret_cast<const float4*>(src + k0 + k4 * 4);
                float* d = Ws + (k4 * 4) * WS_STRIDE + row;
                d[0] = v.x; d[WS_STRIDE] = v.y;
                d[2 * WS_STRIDE] = v.z; d[3 * WS_STRIDE] = v.w;
            }
            __syncthreads();

            const float* xr = Xt + k0 * XT_STRIDE + tmcol;
            const float* wr = Ws + tn3;
            #pragma unroll 8
            for (int kk = 0; kk < 64; ++kk) {
                ulonglong2 A0 = *reinterpret_cast<const ulonglong2*>(xr);
                ulonglong2 A1 = *reinterpret_cast<const ulonglong2*>(xr + 4);
                ull pa[4] = {A0.x, A0.y, A1.x, A1.y};
                ull pb0 = pack2(wr[0]);
                ull pb1 = pack2(wr[1]);
                ull pb2 = pack2(wr[2]);
                #pragma unroll
                for (int i = 0; i < 4; ++i) {
                    ffma2(acc2[i][0], pa[i], pb0);
                    ffma2(acc2[i][1], pa[i], pb1);
                    ffma2(acc2[i][2], pa[i], pb2);
                }
                xr += XT_STRIDE;
                wr += WS_STRIDE;
            }
        }
        __syncthreads();  // Ws reads done before scatter aliases region

        // ---- scatter: Qt (pre-scaled, [d][m]), Kt ([d][m]), Vh ([m][d]) ----
        #pragma unroll
        for (int j = 0; j < 3; ++j) {
            int col = tn3 + j;
            if (col < 32) {
                float bb = bq[h * 32 + col];
                float* d = Qt + col * QK_STRIDE + tm8;
                #pragma unroll
                for (int p = 0; p < 4; ++p) {
                    float2 t = unpack2(acc2[p][j]);
                    *reinterpret_cast<float2*>(d + 2 * p) =
                        make_float2((t.x + bb) * QSCALE, (t.y + bb) * QSCALE);
                }
            } else if (col < 64) {
                int c = col - 32;
                float bb = bk[h * 32 + c];
                float* d = Kt + c * QK_STRIDE + tm8;
                #pragma unroll
                for (int p = 0; p < 4; ++p) {
                    float2 t = unpack2(acc2[p][j]);
                    *reinterpret_cast<float2*>(d + 2 * p) =
                        make_float2(t.x + bb, t.y + bb);
                }
            } else {
                int c = col - 64;
                float bb = bvp[h * 32 + c];
                float* d = Vh + tm8 * 32 + c;
                #pragma unroll
                for (int p = 0; p < 4; ++p) {
                    float2 t = unpack2(acc2[p][j]);
                    d[(2 * p) * 32]     = t.x + bb;
                    d[(2 * p + 1) * 32] = t.y + bb;
                }
            }
        }
        __syncthreads();

        // ---- GEMM1: logits = Qs @ K^T (+bias regs, mask) -> Ls ----
        {
            ull s2[4][2];
            #pragma unroll
            for (int i = 0; i < 4; ++i) { s2[i][0] = 0ull; s2[i][1] = 0ull; }
            #pragma unroll 8
            for (int d = 0; d < 32; ++d) {
                float4 a = *reinterpret_cast<const float4*>(Qt + d * QK_STRIDE + q0a);
                const ull* bp = reinterpret_cast<const ull*>(Kt + d * QK_STRIDE + k0a);
                ull b0 = bp[0], b1 = bp[1];
                ull pa0 = pack2(a.x), pa1 = pack2(a.y), pa2 = pack2(a.z), pa3 = pack2(a.w);
                ffma2(s2[0][0], pa0, b0); ffma2(s2[0][1], pa0, b1);
                ffma2(s2[1][0], pa1, b0); ffma2(s2[1][1], pa1, b1);
                ffma2(s2[2][0], pa2, b0); ffma2(s2[2][1], pa2, b1);
                ffma2(s2[3][0], pa3, b0); ffma2(s2[3][1], pa3, b1);
            }
            const unsigned char* mp = mask + ((size_t)(nw * Hc + h) << 12);
            #pragma unroll
            for (int i = 0; i < 4; ++i) {
                int q = q0a + i;
                unsigned int mw = *reinterpret_cast<const unsigned int*>(mp + q * 64 + k0a);
                float2 p0 = unpack2(s2[i][0]);
                float2 p1 = unpack2(s2[i][1]);
                float v0 = p0.x + bias_r[i][0];
                float v1 = p0.y + bias_r[i][1];
                float v2 = p1.x + bias_r[i][2];
                float v3 = p1.y + bias_r[i][3];
                if (mw) {
                    if (mw & 0x000000ffu) v0 = NEG_INF;
                    if (mw & 0x0000ff00u) v1 = NEG_INF;
                    if (mw & 0x00ff0000u) v2 = NEG_INF;
                    if (mw & 0xff000000u) v3 = NEG_INF;
                }
                *reinterpret_cast<float4*>(Ls + q * LS_STRIDE + k0a) =
                    make_float4(v0, v1, v2, v3);
            }
        }
        __syncthreads();

        // ---- log_softmax, in-place transposed rewrite of Ls ----
        {
            const int q = tid >> 2;
            const int r = tid & 3;
            const float* lp = Ls + q * LS_STRIDE + r * 16;
            float x[16];
            #pragma unroll
            for (int i = 0; i < 4; ++i) {
                float4 v = *reinterpret_cast<const float4*>(lp + i * 4);
                x[4 * i + 0] = v.x; x[4 * i + 1] = v.y;
                x[4 * i + 2] = v.z; x[4 * i + 3] = v.w;
            }
            float mx = x[0];
            #pragma unroll
            for (int i = 1; i < 16; ++i) mx = fmaxf(mx, x[i]);
            mx = fmaxf(mx, __shfl_xor_sync(0xffffffffu, mx, 1));
            mx = fmaxf(mx, __shfl_xor_sync(0xffffffffu, mx, 2));
            float ssum = 0.f;
            #pragma unroll
            for (int i = 0; i < 16; ++i) ssum += __expf(x[i] - mx);
            ssum += __shfl_xor_sync(0xffffffffu, ssum, 1);
            ssum += __shfl_xor_sync(0xffffffffu, ssum, 2);
            float lse = mx + __logf(ssum);
            __syncthreads();  // all reads of Ls complete before transposed writes
            #pragma unroll
            for (int i = 0; i < 16; ++i)
                Ls[(r * 16 + i) * LS_STRIDE + q] = x[i] - lse;
        }
        __syncthreads();

        // ---- GEMM2: out_h = attn @ V (64 x 32), Ls now holds At[k][q] ----
        {
            const int d0 = (tid >> 4) * 2;
            ull o2[4];
            #pragma unroll
            for (int i = 0; i < 4; ++i) o2[i] = 0ull;
            const float* vp = Vh + d0;
            #pragma unroll 8
            for (int k = 0; k < 64; ++k) {
                float4 a = *reinterpret_cast<const float4*>(Ls + k * LS_STRIDE + q0a);
                ull b = *reinterpret_cast<const ull*>(vp + k * 32);
                ffma2(o2[0], pack2(a.x), b);
                ffma2(o2[1], pack2(a.y), b);
                ffma2(o2[2], pack2(a.z), b);
                ffma2(o2[3], pack2(a.w), b);
            }
            #pragma unroll
            for (int i = 0; i < 4; ++i) {
                float2 t = unpack2(o2[i]);
                *reinterpret_cast<float2*>(Og + (q0a + i) * Dc + h * 32 + d0) = t;
            }
        }
        // next head: kt-loop top sync orders GEMM2's Ls/Vh reads before the
        // next Ws staging overwrites the union region.
    }
}

extern "C" void kernel_launch(void* const* d_in, const int* in_sizes, int n_in,
                              void* d_out, int out_size) {
    (void)in_sizes; (void)n_in; (void)out_size;
    const float* patches = (const float*)d_in[0];
    const float* wq = (const float*)d_in[1];
    const float* bq = (const float*)d_in[2];
    const float* wk = (const float*)d_in[3];
    const float* bk = (const float*)d_in[4];
    const float* wv = (const float*)d_in[5];
    const float* bv = (const float*)d_in[6];
    const float* pos = (const float*)d_in[7];
    const unsigned char* mask = (const unsigned char*)d_in[8];
    float* out = (float*)d_out;

    const size_t smem_bytes = (size_t)SMEM_FLOATS * sizeof(float);  // 112640 B
    cudaFuncSetAttribute(swin_attn_kernel,
                         cudaFuncAttributeMaxDynamicSharedMemorySize,
                         (int)smem_bytes);
    swin_attn_kernel<<<16 * 256, THREADS, smem_bytes>>>(
        patches, wq, bq, wk, bk, wv, bv, pos, mask, out);
}

// round 12
// speedup vs baseline: 1.9628x; 1.9628x over previous
#include <cuda_runtime.h>
#include <cuda_fp16.h>
#include <cstdint>
#include <cstddef>

// ---------------------------------------------------------------------------
// SwinSelfAttention fused kernel v6 — mma.sync (fallback HMMA) projection
//   B=16, NW=256, S=64, D=256, H=8, HD=32.
//   CTA = 2 windows (grid 2048, 512 threads, 1 CTA/SM, smem 230400 B).
//   GEMM0 (X @ Wcat^T) via mma.sync.m16n8k16 fp16, 2-term hi/lo split
//     (Ahi*Bhi + Ahi*Blo + Alo*Bhi), f32 accumulate in registers.
//   A/W in SMEM with segment-rotation swizzle -> conflict-free LDS.32 frag
//   loads, no padding. Attention: proven scalar f32x2 path, both windows
//   concurrently on 512 threads.
// ---------------------------------------------------------------------------

namespace {
constexpr int Dc = 256;
constexpr int Hc = 8;
constexpr int NWc = 256;
constexpr int THREADS = 512;
constexpr float QSCALE = 0.17677669529663688f;  // 1/sqrt(32)

// SMEM byte offsets
constexpr int OFF_BIAS  = 0;        // 96 floats (qkv bias of current head)
constexpr int OFF_AHI   = 1024;     // X hi fp16 [128 rows x 512B] = 65536
constexpr int OFF_ALO   = 66560;    // X lo = 65536
constexpr int OFF_UNION = 132096;   // union: W (98304) | attn (2 x 43520)
constexpr int OFF_WHI   = OFF_UNION;            // 96 x 512B = 49152
constexpr int OFF_WLO   = OFF_UNION + 49152;    // 49152 -> end 230400
constexpr int ATT_BYTES = 43520;                // per-window attn block
constexpr int SMEM_BYTES = OFF_WLO + 49152;     // 230400 <= 232448
// attn block float offsets
constexpr int QT_F = 0;       // [32][68]
constexpr int KT_F = 2176;    // [32][68]
constexpr int VH_F = 4352;    // [64][34]
constexpr int LS_F = 6528;    // [64][68]
constexpr int QK_STRIDE = 68;
constexpr int LS_STRIDE = 68;
constexpr int VH_STRIDE = 34;

using ull = unsigned long long;
}  // namespace

// segment-rotation swizzle: element (row, k) of a [rows x 256] fp16 buffer,
// 512B rows; 16B segment index rotated by row -> conflict-free frag loads.
__device__ __forceinline__ unsigned swz(int row, int k) {
    return (unsigned)(row * 512) + ((((k >> 3) + row) & 31) << 4) + ((k & 7) << 1);
}

__device__ __forceinline__ unsigned pack_h2(float a, float b) {
    __half2 h = __floats2half2_rn(a, b);
    return *reinterpret_cast<unsigned*>(&h);
}

__device__ __forceinline__ void mma16816(float* c, const unsigned* a, const unsigned* b) {
    asm volatile(
        "mma.sync.aligned.m16n8k16.row.col.f32.f16.f16.f32 "
        "{%0,%1,%2,%3}, {%4,%5,%6,%7}, {%8,%9}, {%0,%1,%2,%3};"
        : "+f"(c[0]), "+f"(c[1]), "+f"(c[2]), "+f"(c[3])
        : "r"(a[0]), "r"(a[1]), "r"(a[2]), "r"(a[3]), "r"(b[0]), "r"(b[1]));
}

// f32x2 helpers (scalar attention)
__device__ __forceinline__ void ffma2(ull& d, ull a, ull b) {
    asm("fma.rn.f32x2 %0, %1, %2, %0;" : "+l"(d) : "l"(a), "l"(b));
}
__device__ __forceinline__ ull pack2(float x) {
    ull r; unsigned u = __float_as_uint(x);
    asm("mov.b64 %0, {%1, %1};" : "=l"(r) : "r"(u));
    return r;
}
__device__ __forceinline__ float2 unpack2(ull v) {
    unsigned lo, hi;
    asm("mov.b64 {%0, %1}, %2;" : "=r"(lo), "=r"(hi) : "l"(v));
    return make_float2(__uint_as_float(lo), __uint_as_float(hi));
}

__global__ void __launch_bounds__(THREADS, 1)
swin_attn_kernel(const float* __restrict__ patches,
                 const float* __restrict__ wq, const float* __restrict__ bq,
                 const float* __restrict__ wk, const float* __restrict__ bk,
                 const float* __restrict__ wv, const float* __restrict__ bvp,
                 const float* __restrict__ pos_bias,
                 const unsigned char* __restrict__ mask,
                 float* __restrict__ out) {
    extern __shared__ char smem[];
    float* bias_s = reinterpret_cast<float*>(smem + OFF_BIAS);

    const int tid  = threadIdx.x;
    const int w    = tid >> 5;
    const int lane = tid & 31;
    const int gid  = lane >> 2;     // mma group id (0..7)
    const int tig  = lane & 3;      // thread in group
    const int bw2  = blockIdx.x * 2;
    const float NEG_INF = __int_as_float(0xff800000);

    // ---- stage A = X pair -> fp16 hi/lo, swizzled (rows 0-63 win0, 64-127 win1)
    #pragma unroll
    for (int i = 0; i < 16; ++i) {
        int idx = tid + i * THREADS;            // 0..8191 float4s
        int row = idx >> 6;
        int k0 = (idx & 63) * 4;
        const float* src = patches + (size_t)(bw2 + (row >> 6)) * (64 * Dc)
                           + (row & 63) * Dc + k0;
        float4 v = *reinterpret_cast<const float4*>(src);
        float hx = __half2float(__float2half_rn(v.x));
        float hy = __half2float(__float2half_rn(v.y));
        float hz = __half2float(__float2half_rn(v.z));
        float hw = __half2float(__float2half_rn(v.w));
        unsigned off = swz(row, k0);            // k0 % 4 == 0 -> 8B aligned
        *reinterpret_cast<uint2*>(smem + OFF_AHI + off) =
            make_uint2(pack_h2(v.x, v.y), pack_h2(v.z, v.w));
        *reinterpret_cast<uint2*>(smem + OFF_ALO + off) =
            make_uint2(pack_h2(v.x - hx, v.y - hy), pack_h2(v.z - hz, v.w - hw));
    }

    // ---- attention thread mapping + positional-bias registers ----
    const int lt  = tid & 255;
    const int win = tid >> 8;
    const int q0a = (lt & 15) * 4;
    const int k0a = (lt >> 4) * 4;
    float bias_r[4][4];
    #pragma unroll
    for (int i = 0; i < 4; ++i)
        #pragma unroll
        for (int j = 0; j < 4; ++j) {
            int q = q0a + i, k = k0a + j;
            bias_r[i][j] = pos_bias[((q >> 3) - (k >> 3) + 7) * 15 + ((q & 7) - (k & 7) + 7)];
        }
    float* att = reinterpret_cast<float*>(smem + OFF_UNION + win * ATT_BYTES);
    const int nw_w = (bw2 + win) & (NWc - 1);
    float* Og = out + (size_t)(bw2 + win) * (64 * Dc);

    // ---- GEMM0 warp tiling: 4 m-groups x 4 n-groups ----
    const int mg = w >> 2;                       // D rows 32*mg .. +31
    const int ng = w & 3;                        // D cols 24*ng .. +23
    int rA[4], bA[4];                            // A frag rows / byte bases
    #pragma unroll
    for (int i = 0; i < 4; ++i) {
        rA[i] = 32 * mg + 8 * i + gid;           // rows gid, gid+8, gid+16, gid+24
        bA[i] = rA[i] * 512 + tig * 4;
    }
    int rW[3], bW[3];
    #pragma unroll
    for (int i = 0; i < 3; ++i) {
        rW[i] = 24 * ng + 8 * i + gid;
        bW[i] = rW[i] * 512 + tig * 4;
    }

    for (int h = 0; h < Hc; ++h) {
        __syncthreads();  // prior head's attention reads of union done (A done h=0)

        // ---- stage W = Wcat_h -> fp16 hi/lo, swizzled ----
        #pragma unroll
        for (int i = 0; i < 12; ++i) {
            int idx = tid + i * THREADS;        // 0..6143 float4s
            int row = idx >> 6;
            int k0 = (idx & 63) * 4;
            const float* src;
            if (row < 32)      src = wq + (size_t)(h * 32 + row) * Dc;
            else if (row < 64) src = wk + (size_t)(h * 32 + row - 32) * Dc;
            else               src = wv + (size_t)(h * 32 + row - 64) * Dc;
            float4 v = *reinterpret_cast<const float4*>(src + k0);
            float hx = __half2float(__float2half_rn(v.x));
            float hy = __half2float(__float2half_rn(v.y));
            float hz = __half2float(__float2half_rn(v.z));
            float hw = __half2float(__float2half_rn(v.w));
            unsigned off = swz(row, k0);
            *reinterpret_cast<uint2*>(smem + OFF_WHI + off) =
                make_uint2(pack_h2(v.x, v.y), pack_h2(v.z, v.w));
            *reinterpret_cast<uint2*>(smem + OFF_WLO + off) =
                make_uint2(pack_h2(v.x - hx, v.y - hy), pack_h2(v.z - hz, v.w - hw));
        }
        if (tid < 96) {
            float b;
            if (tid < 32)      b = bq[h * 32 + tid];
            else if (tid < 64) b = bk[h * 32 + tid - 32];
            else               b = bvp[h * 32 + tid - 64];
            bias_s[tid] = b;
        }
        __syncthreads();

        // ---- mma mainloop: D[128x96] = Xhi*Whi + Xhi*Wlo + Xlo*Whi, K=256 ----
        float acc[6][4];                         // [mt*3+nt][c0..c3]
        #pragma unroll
        for (int t = 0; t < 6; ++t)
            #pragma unroll
            for (int c = 0; c < 4; ++c) acc[t][c] = 0.f;

        #pragma unroll 2
        for (int s = 0; s < 32; s += 2) {        // s = k>>3; k16 per step
            unsigned ah[2][4], al[2][4];
            #pragma unroll
            for (int mt = 0; mt < 2; ++mt) {
                const int i0 = 2 * mt, i1 = 2 * mt + 1;
                unsigned o00 = bA[i0] + (((s + rA[i0]) & 31) << 4);
                unsigned o10 = bA[i1] + (((s + rA[i1]) & 31) << 4);
                unsigned o01 = bA[i0] + (((s + 1 + rA[i0]) & 31) << 4);
                unsigned o11 = bA[i1] + (((s + 1 + rA[i1]) & 31) << 4);
                ah[mt][0] = *reinterpret_cast<const unsigned*>(smem + OFF_AHI + o00);
                ah[mt][1] = *reinterpret_cast<const unsigned*>(smem + OFF_AHI + o10);
                ah[mt][2] = *reinterpret_cast<const unsigned*>(smem + OFF_AHI + o01);
                ah[mt][3] = *reinterpret_cast<const unsigned*>(smem + OFF_AHI + o11);
                al[mt][0] = *reinterpret_cast<const unsigned*>(smem + OFF_ALO + o00);
                al[mt][1] = *reinterpret_cast<const unsigned*>(smem + OFF_ALO + o10);
                al[mt][2] = *reinterpret_cast<const unsigned*>(smem + OFF_ALO + o01);
                al[mt][3] = *reinterpret_cast<const unsigned*>(smem + OFF_ALO + o11);
            }
            #pragma unroll
            for (int nt = 0; nt < 3; ++nt) {
                unsigned o0 = bW[nt] + (((s + rW[nt]) & 31) << 4);
                unsigned o1 = bW[nt] + (((s + 1 + rW[nt]) & 31) << 4);
                unsigned bh[2], bl[2];
                bh[0] = *reinterpret_cast<const unsigned*>(smem + OFF_WHI + o0);
                bh[1] = *reinterpret_cast<const unsigned*>(smem + OFF_WHI + o1);
                bl[0] = *reinterpret_cast<const unsigned*>(smem + OFF_WLO + o0);
                bl[1] = *reinterpret_cast<const unsigned*>(smem + OFF_WLO + o1);
                #pragma unroll
                for (int mt = 0; mt < 2; ++mt) {
                    mma16816(acc[mt * 3 + nt], ah[mt], bh);
                    mma16816(acc[mt * 3 + nt], ah[mt], bl);
                    mma16816(acc[mt * 3 + nt], al[mt], bh);
                }
            }
        }
        __syncthreads();  // all W smem reads done before union becomes attn bufs

        // ---- scatter accumulators + bias -> Qt/Kt/Vh (per output window) ----
        #pragma unroll
        for (int mt = 0; mt < 2; ++mt)
            #pragma unroll
            for (int nt = 0; nt < 3; ++nt)
                #pragma unroll
                for (int rr = 0; rr < 2; ++rr) {
                    int R = 32 * mg + 16 * mt + 8 * rr + gid;
                    int wv2 = R >> 6, m = R & 63;
                    float* ab = reinterpret_cast<float*>(
                        smem + OFF_UNION + wv2 * ATT_BYTES);
                    #pragma unroll
                    for (int cc = 0; cc < 2; ++cc) {
                        int C = 24 * ng + 8 * nt + 2 * tig + cc;
                        float v = acc[mt * 3 + nt][rr * 2 + cc] + bias_s[C];
                        if (C < 32)      ab[QT_F + C * QK_STRIDE + m] = v * QSCALE;
                        else if (C < 64) ab[KT_F + (C - 32) * QK_STRIDE + m] = v;
                        else             ab[VH_F + m * VH_STRIDE + (C - 64)] = v;
                    }
                }
        __syncthreads();

        // =================== scalar attention (both windows) =================
        const float* Qh = att + QT_F;
        const float* Kh = att + KT_F;
        const float* Vp = att + VH_F;
        float* Ls = att + LS_F;

        // ---- GEMM1: logits = Qs @ K^T (+bias regs, mask) -> Ls ----
        {
            ull s2[4][2];
            #pragma unroll
            for (int i = 0; i < 4; ++i) { s2[i][0] = 0ull; s2[i][1] = 0ull; }
            #pragma unroll 8
            for (int d = 0; d < 32; ++d) {
                float4 a = *reinterpret_cast<const float4*>(Qh + d * QK_STRIDE + q0a);
                const ull* bp = reinterpret_cast<const ull*>(Kh + d * QK_STRIDE + k0a);
                ull b0 = bp[0], b1 = bp[1];
                ull pa0 = pack2(a.x), pa1 = pack2(a.y), pa2 = pack2(a.z), pa3 = pack2(a.w);
                ffma2(s2[0][0], pa0, b0); ffma2(s2[0][1], pa0, b1);
                ffma2(s2[1][0], pa1, b0); ffma2(s2[1][1], pa1, b1);
                ffma2(s2[2][0], pa2, b0); ffma2(s2[2][1], pa2, b1);
                ffma2(s2[3][0], pa3, b0); ffma2(s2[3][1], pa3, b1);
            }
            const unsigned char* mp = mask + ((size_t)(nw_w * Hc + h) << 12);
            #pragma unroll
            for (int i = 0; i < 4; ++i) {
                int q = q0a + i;
                unsigned mw = *reinterpret_cast<const unsigned*>(mp + q * 64 + k0a);
                float2 p0 = unpack2(s2[i][0]);
                float2 p1 = unpack2(s2[i][1]);
                float v0 = p0.x + bias_r[i][0];
                float v1 = p0.y + bias_r[i][1];
                float v2 = p1.x + bias_r[i][2];
                float v3 = p1.y + bias_r[i][3];
                if (mw) {
                    if (mw & 0x000000ffu) v0 = NEG_INF;
                    if (mw & 0x0000ff00u) v1 = NEG_INF;
                    if (mw & 0x00ff0000u) v2 = NEG_INF;
                    if (mw & 0xff000000u) v3 = NEG_INF;
                }
                *reinterpret_cast<float4*>(Ls + q * LS_STRIDE + k0a) =
                    make_float4(v0, v1, v2, v3);
            }
        }
        __syncthreads();

        // ---- log_softmax, in-place transposed rewrite of Ls ----
        {
            const int q = lt >> 2;
            const int r = lt & 3;
            const float* lp = Ls + q * LS_STRIDE + r * 16;
            float x[16];
            #pragma unroll
            for (int i = 0; i < 4; ++i) {
                float4 v = *reinterpret_cast<const float4*>(lp + i * 4);
                x[4 * i + 0] = v.x; x[4 * i + 1] = v.y;
                x[4 * i + 2] = v.z; x[4 * i + 3] = v.w;
            }
            float mx = x[0];
            #pragma unroll
            for (int i = 1; i < 16; ++i) mx = fmaxf(mx, x[i]);
            mx = fmaxf(mx, __shfl_xor_sync(0xffffffffu, mx, 1));
            mx = fmaxf(mx, __shfl_xor_sync(0xffffffffu, mx, 2));
            float ssum = 0.f;
            #pragma unroll
            for (int i = 0; i < 16; ++i) ssum += __expf(x[i] - mx);
            ssum += __shfl_xor_sync(0xffffffffu, ssum, 1);
            ssum += __shfl_xor_sync(0xffffffffu, ssum, 2);
            float lse = mx + __logf(ssum);
            __syncthreads();  // all Ls reads done before transposed writes
            #pragma unroll
            for (int i = 0; i < 16; ++i)
                Ls[(r * 16 + i) * LS_STRIDE + q] = x[i] - lse;
        }
        __syncthreads();

        // ---- GEMM2: out_h = attn @ V (64 x 32), Ls holds At[k][q] ----
        {
            const int d0 = (lt >> 4) * 2;
            ull o2[4];
            #pragma unroll
            for (int i = 0; i < 4; ++i) o2[i] = 0ull;
            const float* vp = Vp + d0;
            #pragma unroll 8
            for (int k = 0; k < 64; ++k) {
                float4 a = *reinterpret_cast<const float4*>(Ls + k * LS_STRIDE + q0a);
                ull b = *reinterpret_cast<const ull*>(vp + k * VH_STRIDE);
                ffma2(o2[0], pack2(a.x), b);
                ffma2(o2[1], pack2(a.y), b);
                ffma2(o2[2], pack2(a.z), b);
                ffma2(o2[3], pack2(a.w), b);
            }
            #pragma unroll
            for (int i = 0; i < 4; ++i) {
                float2 t = unpack2(o2[i]);
                *reinterpret_cast<float2*>(Og + (q0a + i) * Dc + h * 32 + d0) = t;
            }
        }
        // head-loop top sync orders these union reads before next W staging
    }
}

extern "C" void kernel_launch(void* const* d_in, const int* in_sizes, int n_in,
                              void* d_out, int out_size) {
    (void)in_sizes; (void)n_in; (void)out_size;
    const float* patches = (const float*)d_in[0];
    const float* wq = (const float*)d_in[1];
    const float* bq = (const float*)d_in[2];
    const float* wk = (const float*)d_in[3];
    const float* bk = (const float*)d_in[4];
    const float* wv = (const float*)d_in[5];
    const float* bv = (const float*)d_in[6];
    const float* pos = (const float*)d_in[7];
    const unsigned char* mask = (const unsigned char*)d_in[8];
    float* out = (float*)d_out;

    cudaFuncSetAttribute(swin_attn_kernel,
                         cudaFuncAttributeMaxDynamicSharedMemorySize, SMEM_BYTES);
    swin_attn_kernel<<<2048, THREADS, SMEM_BYTES>>>(
        patches, wq, bq, wk, bk, wv, bv, pos, mask, out);
}

// round 16
// speedup vs baseline: 2.1494x; 1.0950x over previous
#include <cuda_runtime.h>
#include <cuda_fp16.h>
#include <cstdint>
#include <cstddef>

// ---------------------------------------------------------------------------
// SwinSelfAttention fused kernel v7 — mma.sync projection + ldmatrix + W-prepass
//   (byte-identical resubmit; R13 bench was a broker/container failure)
//   B=16, NW=256, S=64, D=256, H=8, HD=32.
//   Prepass kernel: W -> pre-swizzled fp16 hi/lo __device__ buffers (once).
//   Main: CTA = 2 windows (grid 2048, 512 threads, smem 230400 B).
//     GEMM0 via mma.sync.m16n8k16 fp16 2-term split, frags via ldmatrix.
//     Attention: scalar f32x2 path, both windows concurrently.
// ---------------------------------------------------------------------------

namespace {
constexpr int Dc = 256;
constexpr int Hc = 8;
constexpr int NWc = 256;
constexpr int THREADS = 512;
constexpr float QSCALE = 0.17677669529663688f;  // 1/sqrt(32)

constexpr int OFF_BIAS  = 0;
constexpr int OFF_AHI   = 1024;
constexpr int OFF_ALO   = 66560;
constexpr int OFF_UNION = 132096;
constexpr int OFF_WHI   = OFF_UNION;
constexpr int OFF_WLO   = OFF_UNION + 49152;
constexpr int ATT_BYTES = 43520;
constexpr int SMEM_BYTES = OFF_WLO + 49152;     // 230400
constexpr int QT_F = 0;
constexpr int KT_F = 2176;
constexpr int VH_F = 4352;
constexpr int LS_F = 6528;
constexpr int QK_STRIDE = 68;
constexpr int LS_STRIDE = 68;
constexpr int VH_STRIDE = 34;
constexpr int W_BYTES = 96 * 512;               // one head, one half: 49152

using ull = unsigned long long;
}  // namespace

// pre-swizzled fp16 W images, [head][bytes]
__device__ __align__(16) unsigned char g_whi[Hc][W_BYTES];
__device__ __align__(16) unsigned char g_wlo[Hc][W_BYTES];

// segment-rotation swizzle: element (row, k) of [rows x 256] fp16, 512B rows
__device__ __forceinline__ unsigned swz(int row, int k) {
    return (unsigned)(row * 512) + ((((k >> 3) + row) & 31) << 4) + ((k & 7) << 1);
}
__device__ __forceinline__ unsigned pack_h2(float a, float b) {
    __half2 h = __floats2half2_rn(a, b);
    return *reinterpret_cast<unsigned*>(&h);
}
__device__ __forceinline__ unsigned smem_u32(const void* p) {
    unsigned a;
    asm("{ .reg .u64 t; cvta.to.shared.u64 t, %1; cvt.u32.u64 %0, t; }"
        : "=r"(a) : "l"(p));
    return a;
}
__device__ __forceinline__ void mma16816(float* c, const unsigned* a, const unsigned* b) {
    asm volatile(
        "mma.sync.aligned.m16n8k16.row.col.f32.f16.f16.f32 "
        "{%0,%1,%2,%3}, {%4,%5,%6,%7}, {%8,%9}, {%0,%1,%2,%3};"
        : "+f"(c[0]), "+f"(c[1]), "+f"(c[2]), "+f"(c[3])
        : "r"(a[0]), "r"(a[1]), "r"(a[2]), "r"(a[3]), "r"(b[0]), "r"(b[1]));
}
__device__ __forceinline__ void ldsm_x4(unsigned* r, unsigned addr) {
    asm volatile("ldmatrix.sync.aligned.m8n8.x4.shared.b16 {%0,%1,%2,%3}, [%4];"
                 : "=r"(r[0]), "=r"(r[1]), "=r"(r[2]), "=r"(r[3]) : "r"(addr));
}
__device__ __forceinline__ void ldsm_x2(unsigned* r, unsigned addr) {
    asm volatile("ldmatrix.sync.aligned.m8n8.x2.shared.b16 {%0,%1}, [%2];"
                 : "=r"(r[0]), "=r"(r[1]) : "r"(addr));
}
// f32x2 helpers
__device__ __forceinline__ void ffma2(ull& d, ull a, ull b) {
    asm("fma.rn.f32x2 %0, %1, %2, %0;" : "+l"(d) : "l"(a), "l"(b));
}
__device__ __forceinline__ ull pack2(float x) {
    ull r; unsigned u = __float_as_uint(x);
    asm("mov.b64 %0, {%1, %1};" : "=l"(r) : "r"(u));
    return r;
}
__device__ __forceinline__ float2 unpack2(ull v) {
    unsigned lo, hi;
    asm("mov.b64 {%0, %1}, %2;" : "=r"(lo), "=r"(hi) : "l"(v));
    return make_float2(__uint_as_float(lo), __uint_as_float(hi));
}

// ---------------- prepass: W -> swizzled fp16 hi/lo globals ------------------
__global__ void prep_w_kernel(const float* __restrict__ wq,
                              const float* __restrict__ wk,
                              const float* __restrict__ wv) {
    int idx = blockIdx.x * blockDim.x + threadIdx.x;   // 0..49151 float4 units
    int h   = idx / (96 * 64);
    int rem = idx - h * (96 * 64);
    int row = rem >> 6;
    int k0  = (rem & 63) * 4;
    const float* src;
    if (row < 32)      src = wq + (size_t)(h * 32 + row) * Dc;
    else if (row < 64) src = wk + (size_t)(h * 32 + row - 32) * Dc;
    else               src = wv + (size_t)(h * 32 + row - 64) * Dc;
    float4 v = *reinterpret_cast<const float4*>(src + k0);
    float hx = __half2float(__float2half_rn(v.x));
    float hy = __half2float(__float2half_rn(v.y));
    float hz = __half2float(__float2half_rn(v.z));
    float hw = __half2float(__float2half_rn(v.w));
    unsigned off = swz(row, k0);
    *reinterpret_cast<uint2*>(g_whi[h] + off) =
        make_uint2(pack_h2(v.x, v.y), pack_h2(v.z, v.w));
    *reinterpret_cast<uint2*>(g_wlo[h] + off) =
        make_uint2(pack_h2(v.x - hx, v.y - hy), pack_h2(v.z - hz, v.w - hw));
}

// ---------------------------------- main -------------------------------------
__global__ void __launch_bounds__(THREADS, 1)
swin_attn_kernel(const float* __restrict__ patches,
                 const float* __restrict__ wq, const float* __restrict__ bq,
                 const float* __restrict__ wk, const float* __restrict__ bk,
                 const float* __restrict__ wv, const float* __restrict__ bvp,
                 const float* __restrict__ pos_bias,
                 const unsigned char* __restrict__ mask,
                 float* __restrict__ out) {
    extern __shared__ char smem[];
    float* bias_s = reinterpret_cast<float*>(smem + OFF_BIAS);
    const unsigned sbase = smem_u32(smem);

    const int tid  = threadIdx.x;
    const int w    = tid >> 5;
    const int lane = tid & 31;
    const int gid  = lane >> 2;
    const int tig  = lane & 3;
    const int bw2  = blockIdx.x * 2;
    const float NEG_INF = __int_as_float(0xff800000);

    // ---- stage A = X pair -> fp16 hi/lo, swizzled ----
    #pragma unroll
    for (int i = 0; i < 16; ++i) {
        int idx = tid + i * THREADS;
        int row = idx >> 6;
        int k0 = (idx & 63) * 4;
        const float* src = patches + (size_t)(bw2 + (row >> 6)) * (64 * Dc)
                           + (row & 63) * Dc + k0;
        float4 v = *reinterpret_cast<const float4*>(src);
        float hx = __half2float(__float2half_rn(v.x));
        float hy = __half2float(__float2half_rn(v.y));
        float hz = __half2float(__float2half_rn(v.z));
        float hw = __half2float(__float2half_rn(v.w));
        unsigned off = swz(row, k0);
        *reinterpret_cast<uint2*>(smem + OFF_AHI + off) =
            make_uint2(pack_h2(v.x, v.y), pack_h2(v.z, v.w));
        *reinterpret_cast<uint2*>(smem + OFF_ALO + off) =
            make_uint2(pack_h2(v.x - hx, v.y - hy), pack_h2(v.z - hz, v.w - hw));
    }

    // ---- attention mapping + positional bias regs ----
    const int lt  = tid & 255;
    const int win = tid >> 8;
    const int q0a = (lt & 15) * 4;
    const int k0a = (lt >> 4) * 4;
    float bias_r[4][4];
    #pragma unroll
    for (int i = 0; i < 4; ++i)
        #pragma unroll
        for (int j = 0; j < 4; ++j) {
            int q = q0a + i, k = k0a + j;
            bias_r[i][j] = pos_bias[((q >> 3) - (k >> 3) + 7) * 15 + ((q & 7) - (k & 7) + 7)];
        }
    float* att = reinterpret_cast<float*>(smem + OFF_UNION + win * ATT_BYTES);
    const int nw_w = (bw2 + win) & (NWc - 1);
    float* Og = out + (size_t)(bw2 + win) * (64 * Dc);

    // ---- GEMM0 warp tiling + ldmatrix lane constants ----
    const int mg = w >> 2;
    const int ng = w & 3;
    unsigned abA[2]; int rotA[2];
    #pragma unroll
    for (int mt = 0; mt < 2; ++mt) {
        int r = 32 * mg + 16 * mt + (lane & 15);
        abA[mt] = (unsigned)(r * 512);
        rotA[mt] = ((lane >> 4) + r) & 31;
    }
    unsigned abW[3]; int rotW[3];
    #pragma unroll
    for (int nt = 0; nt < 3; ++nt) {
        int r = 24 * ng + 8 * nt + (lane & 7);
        abW[nt] = (unsigned)(r * 512);
        rotW[nt] = (((lane >> 3) & 1) + r) & 31;
    }
    const unsigned AHIb = sbase + OFF_AHI, ALOb = sbase + OFF_ALO;
    const unsigned WHIb = sbase + OFF_WHI, WLOb = sbase + OFF_WLO;

    for (int h = 0; h < Hc; ++h) {
        __syncthreads();  // prior head's union reads done (A staging done h=0)

        // ---- stage W: pure copy from pre-swizzled globals ----
        {
            const uint4* sh = reinterpret_cast<const uint4*>(g_whi[h]);
            const uint4* sl = reinterpret_cast<const uint4*>(g_wlo[h]);
            uint4* dh = reinterpret_cast<uint4*>(smem + OFF_WHI);
            uint4* dl = reinterpret_cast<uint4*>(smem + OFF_WLO);
            #pragma unroll
            for (int i = 0; i < 6; ++i) {
                int j = tid + i * THREADS;        // 0..3071
                dh[j] = sh[j];
                dl[j] = sl[j];
            }
        }
        if (tid < 96) {
            float b;
            if (tid < 32)      b = bq[h * 32 + tid];
            else if (tid < 64) b = bk[h * 32 + tid - 32];
            else               b = bvp[h * 32 + tid - 64];
            bias_s[tid] = b;
        }
        __syncthreads();

        // ---- mma mainloop: D[128x96] = Xhi*Whi + Xhi*Wlo + Xlo*Whi, K=256 ----
        float acc[6][4];
        #pragma unroll
        for (int t = 0; t < 6; ++t)
            #pragma unroll
            for (int c = 0; c < 4; ++c) acc[t][c] = 0.f;

        #pragma unroll 4
        for (int st = 0; st < 16; ++st) {         // one k16 step
            const int s2 = 2 * st;
            unsigned ah[2][4], al[2][4];
            #pragma unroll
            for (int mt = 0; mt < 2; ++mt) {
                unsigned off = abA[mt] + (((s2 + rotA[mt]) & 31) << 4);
                ldsm_x4(ah[mt], AHIb + off);
                ldsm_x4(al[mt], ALOb + off);
            }
            #pragma unroll
            for (int nt = 0; nt < 3; ++nt) {
                unsigned offw = abW[nt] + (((s2 + rotW[nt]) & 31) << 4);
                unsigned bh[2], bl[2];
                ldsm_x2(bh, WHIb + offw);
                ldsm_x2(bl, WLOb + offw);
                #pragma unroll
                for (int mt = 0; mt < 2; ++mt) {
                    mma16816(acc[mt * 3 + nt], ah[mt], bh);
                    mma16816(acc[mt * 3 + nt], ah[mt], bl);
                    mma16816(acc[mt * 3 + nt], al[mt], bh);
                }
            }
        }
        __syncthreads();  // W smem reads done before union becomes attn bufs

        // ---- scatter accumulators + bias -> Qt/Kt/Vh ----
        #pragma unroll
        for (int mt = 0; mt < 2; ++mt)
            #pragma unroll
            for (int nt = 0; nt < 3; ++nt)
                #pragma unroll
                for (int rr = 0; rr < 2; ++rr) {
                    int R = 32 * mg + 16 * mt + 8 * rr + gid;
                    int wv2 = R >> 6, m = R & 63;
                    float* ab = reinterpret_cast<float*>(
                        smem + OFF_UNION + wv2 * ATT_BYTES);
                    #pragma unroll
                    for (int cc = 0; cc < 2; ++cc) {
                        int C = 24 * ng + 8 * nt + 2 * tig + cc;
                        float v = acc[mt * 3 + nt][rr * 2 + cc] + bias_s[C];
                        if (C < 32)      ab[QT_F + C * QK_STRIDE + m] = v * QSCALE;
                        else if (C < 64) ab[KT_F + (C - 32) * QK_STRIDE + m] = v;
                        else             ab[VH_F + m * VH_STRIDE + (C - 64)] = v;
                    }
                }
        __syncthreads();

        // =================== scalar attention (both windows) =================
        const float* Qh = att + QT_F;
        const float* Kh = att + KT_F;
        const float* Vp = att + VH_F;
        float* Ls = att + LS_F;

        // ---- GEMM1: logits = Qs @ K^T (+bias regs, mask) -> Ls ----
        {
            // prefetch mask words early (hidden under the k-loop)
            const unsigned char* mp = mask + ((size_t)(nw_w * Hc + h) << 12);
            unsigned mw_r[4];
            #pragma unroll
            for (int i = 0; i < 4; ++i)
                mw_r[i] = *reinterpret_cast<const unsigned*>(mp + (q0a + i) * 64 + k0a);

            ull s2[4][2];
            #pragma unroll
            for (int i = 0; i < 4; ++i) { s2[i][0] = 0ull; s2[i][1] = 0ull; }
            #pragma unroll 8
            for (int d = 0; d < 32; ++d) {
                float4 a = *reinterpret_cast<const float4*>(Qh + d * QK_STRIDE + q0a);
                const ull* bp = reinterpret_cast<const ull*>(Kh + d * QK_STRIDE + k0a);
                ull b0 = bp[0], b1 = bp[1];
                ull pa0 = pack2(a.x), pa1 = pack2(a.y), pa2 = pack2(a.z), pa3 = pack2(a.w);
                ffma2(s2[0][0], pa0, b0); ffma2(s2[0][1], pa0, b1);
                ffma2(s2[1][0], pa1, b0); ffma2(s2[1][1], pa1, b1);
                ffma2(s2[2][0], pa2, b0); ffma2(s2[2][1], pa2, b1);
                ffma2(s2[3][0], pa3, b0); ffma2(s2[3][1], pa3, b1);
            }
            #pragma unroll
            for (int i = 0; i < 4; ++i) {
                int q = q0a + i;
                float2 p0 = unpack2(s2[i][0]);
                float2 p1 = unpack2(s2[i][1]);
                float v0 = p0.x + bias_r[i][0];
                float v1 = p0.y + bias_r[i][1];
                float v2 = p1.x + bias_r[i][2];
                float v3 = p1.y + bias_r[i][3];
                if (mw_r[i]) {
                    if (mw_r[i] & 0x000000ffu) v0 = NEG_INF;
                    if (mw_r[i] & 0x0000ff00u) v1 = NEG_INF;
                    if (mw_r[i] & 0x00ff0000u) v2 = NEG_INF;
                    if (mw_r[i] & 0xff000000u) v3 = NEG_INF;
                }
                *reinterpret_cast<float4*>(Ls + q * LS_STRIDE + k0a) =
                    make_float4(v0, v1, v2, v3);
            }
        }
        __syncthreads();

        // ---- log_softmax, in-place transposed rewrite of Ls ----
        {
            const int q = lt >> 2;
            const int r = lt & 3;
            const float* lp = Ls + q * LS_STRIDE + r * 16;
            float x[16];
            #pragma unroll
            for (int i = 0; i < 4; ++i) {
                float4 v = *reinterpret_cast<const float4*>(lp + i * 4);
                x[4 * i + 0] = v.x; x[4 * i + 1] = v.y;
                x[4 * i + 2] = v.z; x[4 * i + 3] = v.w;
            }
            float mx = x[0];
            #pragma unroll
            for (int i = 1; i < 16; ++i) mx = fmaxf(mx, x[i]);
            mx = fmaxf(mx, __shfl_xor_sync(0xffffffffu, mx, 1));
            mx = fmaxf(mx, __shfl_xor_sync(0xffffffffu, mx, 2));
            float ssum = 0.f;
            #pragma unroll
            for (int i = 0; i < 16; ++i) ssum += __expf(x[i] - mx);
            ssum += __shfl_xor_sync(0xffffffffu, ssum, 1);
            ssum += __shfl_xor_sync(0xffffffffu, ssum, 2);
            float lse = mx + __logf(ssum);
            __syncthreads();
            #pragma unroll
            for (int i = 0; i < 16; ++i)
                Ls[(r * 16 + i) * LS_STRIDE + q] = x[i] - lse;
        }
        __syncthreads();

        // ---- GEMM2: out_h = attn @ V (64 x 32) ----
        {
            const int d0 = (lt >> 4) * 2;
            ull o2[4];
            #pragma unroll
            for (int i = 0; i < 4; ++i) o2[i] = 0ull;
            const float* vp = Vp + d0;
            #pragma unroll 8
            for (int k = 0; k < 64; ++k) {
                float4 a = *reinterpret_cast<const float4*>(Ls + k * LS_STRIDE + q0a);
                ull b = *reinterpret_cast<const ull*>(vp + k * VH_STRIDE);
                ffma2(o2[0], pack2(a.x), b);
                ffma2(o2[1], pack2(a.y), b);
                ffma2(o2[2], pack2(a.z), b);
                ffma2(o2[3], pack2(a.w), b);
            }
            #pragma unroll
            for (int i = 0; i < 4; ++i) {
                float2 t = unpack2(o2[i]);
                *reinterpret_cast<float2*>(Og + (q0a + i) * Dc + h * 32 + d0) = t;
            }
        }
        // head-loop top sync orders these union reads before next W staging
    }
}

extern "C" void kernel_launch(void* const* d_in, const int* in_sizes, int n_in,
                              void* d_out, int out_size) {
    (void)in_sizes; (void)n_in; (void)out_size;
    const float* patches = (const float*)d_in[0];
    const float* wq = (const float*)d_in[1];
    const float* bq = (const float*)d_in[2];
    const float* wk = (const float*)d_in[3];
    const float* bk = (const float*)d_in[4];
    const float* wv = (const float*)d_in[5];
    const float* bv = (const float*)d_in[6];
    const float* pos = (const float*)d_in[7];
    const unsigned char* mask = (const unsigned char*)d_in[8];
    float* out = (float*)d_out;

    prep_w_kernel<<<96, 512>>>(wq, wk, wv);

    cudaFuncSetAttribute(swin_attn_kernel,
                         cudaFuncAttributeMaxDynamicSharedMemorySize, SMEM_BYTES);
    swin_attn_kernel<<<2048, THREADS, SMEM_BYTES>>>(
        patches, wq, bq, wk, bk, wv, bv, pos, mask, out);
}

// round 17
// speedup vs baseline: 2.9088x; 1.3533x over previous
#include <cuda_runtime.h>
#include <cuda_fp16.h>
#include <cstdint>
#include <cstddef>

// ---------------------------------------------------------------------------
// SwinSelfAttention fused kernel v8 — full tensor-core path
//   B=16, NW=256, S=64, D=256, H=8, HD=32.
//   Prepass: W -> pre-swizzled fp16 hi/lo globals (once).
//   Main: CTA = 2 windows (grid 2048, 512 threads, smem 230400 B).
//     GEMM0: mma.sync m16n8k16 fp16 3-term split (A=X 128x256, B=W 96x256).
//     GEMM1: mma.sync, S = Q@K^T per window (2x 64x64, k=32), fp16 split.
//     softmax: scalar (512 thr), writes attn as fp16 hi/lo.
//     GEMM2: mma.sync, out = attn@V (2x 64x32, k=64), fp16 split.
// ---------------------------------------------------------------------------

namespace {
constexpr int Dc = 256;
constexpr int Hc = 8;
constexpr int NWc = 256;
constexpr int THREADS = 512;
constexpr float QSCALE = 0.17677669529663688f;  // 1/sqrt(32)

constexpr int OFF_BIAS  = 0;        // 96 floats
constexpr int OFF_AHI   = 1024;     // X hi fp16 [128 x 512B rows] = 65536
constexpr int OFF_ALO   = 66560;
constexpr int OFF_U     = 132096;   // 98304-byte union window
// union members (time-disjoint, barrier-guarded):
//   W:   WHI @ +0 (49152), WLO @ +49152                      [staging+mainloop]
//   Qs/Ks fp16 hi/lo, 64B rows: QSH@+0 QSL@+8192 KSH@+16384 KSL@+24576 [scatter->G1 mma]
//   Ls f32 [128][68] = 34816 @ +0                            [G1 epi -> softmax read]
//   As fp16 hi/lo, 128B rows: ASH@+0 (16384) ASL@+16384      [softmax write -> G2]
//   Vt fp16 hi/lo, 128B rows: VTH@+35840 (8192) VTL@+44032   [scatter -> G2]
constexpr int OFF_WHI = OFF_U;
constexpr int OFF_WLO = OFF_U + 49152;
constexpr int OFF_QSH = OFF_U;
constexpr int OFF_QSL = OFF_U + 8192;
constexpr int OFF_KSH = OFF_U + 16384;
constexpr int OFF_KSL = OFF_U + 24576;
constexpr int OFF_LS  = OFF_U;            // f32, stride 68 floats
constexpr int OFF_ASH = OFF_U;
constexpr int OFF_ASL = OFF_U + 16384;
constexpr int OFF_VTH = OFF_U + 35840;
constexpr int OFF_VTL = OFF_U + 44032;
constexpr int SMEM_BYTES = OFF_U + 98304;   // 230400
constexpr int W_BYTES = 96 * 512;

using ull = unsigned long long;
}  // namespace

__device__ __align__(16) unsigned char g_whi[Hc][W_BYTES];
__device__ __align__(16) unsigned char g_wlo[Hc][W_BYTES];

// swizzles: seg-rotation within a row
__device__ __forceinline__ unsigned swz512(int row, int k) {  // 512B rows (X/W), k in halves
    return (unsigned)(row * 512) + ((((k >> 3) + row) & 31) << 4) + ((k & 7) << 1);
}
__device__ __forceinline__ unsigned swz64(int row, int k) {   // 64B rows (Qs/Ks), k<32
    return (unsigned)(row * 64) + ((((k >> 3) + row) & 3) << 4) + ((k & 7) << 1);
}
__device__ __forceinline__ unsigned swz128(int row, int k) {  // 128B rows (As/Vt), k<64
    return (unsigned)(row * 128) + ((((k >> 3) + row) & 7) << 4) + ((k & 7) << 1);
}
__device__ __forceinline__ unsigned pack_h2(float a, float b) {
    __half2 h = __floats2half2_rn(a, b);
    return *reinterpret_cast<unsigned*>(&h);
}
__device__ __forceinline__ unsigned smem_u32(const void* p) {
    unsigned a;
    asm("{ .reg .u64 t; cvta.to.shared.u64 t, %1; cvt.u32.u64 %0, t; }"
        : "=r"(a) : "l"(p));
    return a;
}
__device__ __forceinline__ void mma16816(float* c, const unsigned* a, const unsigned* b) {
    asm volatile(
        "mma.sync.aligned.m16n8k16.row.col.f32.f16.f16.f32 "
        "{%0,%1,%2,%3}, {%4,%5,%6,%7}, {%8,%9}, {%0,%1,%2,%3};"
        : "+f"(c[0]), "+f"(c[1]), "+f"(c[2]), "+f"(c[3])
        : "r"(a[0]), "r"(a[1]), "r"(a[2]), "r"(a[3]), "r"(b[0]), "r"(b[1]));
}
__device__ __forceinline__ void ldsm_x4(unsigned* r, unsigned addr) {
    asm volatile("ldmatrix.sync.aligned.m8n8.x4.shared.b16 {%0,%1,%2,%3}, [%4];"
                 : "=r"(r[0]), "=r"(r[1]), "=r"(r[2]), "=r"(r[3]) : "r"(addr));
}
__device__ __forceinline__ void ldsm_x2(unsigned* r, unsigned addr) {
    asm volatile("ldmatrix.sync.aligned.m8n8.x2.shared.b16 {%0,%1}, [%2];"
                 : "=r"(r[0]), "=r"(r[1]) : "r"(addr));
}

// ---------------- prepass: W -> swizzled fp16 hi/lo globals ------------------
__global__ void prep_w_kernel(const float* __restrict__ wq,
                              const float* __restrict__ wk,
                              const float* __restrict__ wv) {
    int idx = blockIdx.x * blockDim.x + threadIdx.x;
    int h   = idx / (96 * 64);
    int rem = idx - h * (96 * 64);
    int row = rem >> 6;
    int k0  = (rem & 63) * 4;
    const float* src;
    if (row < 32)      src = wq + (size_t)(h * 32 + row) * Dc;
    else if (row < 64) src = wk + (size_t)(h * 32 + row - 32) * Dc;
    else               src = wv + (size_t)(h * 32 + row - 64) * Dc;
    float4 v = *reinterpret_cast<const float4*>(src + k0);
    float hx = __half2float(__float2half_rn(v.x));
    float hy = __half2float(__float2half_rn(v.y));
    float hz = __half2float(__float2half_rn(v.z));
    float hw = __half2float(__float2half_rn(v.w));
    unsigned off = swz512(row, k0);
    *reinterpret_cast<uint2*>(g_whi[h] + off) =
        make_uint2(pack_h2(v.x, v.y), pack_h2(v.z, v.w));
    *reinterpret_cast<uint2*>(g_wlo[h] + off) =
        make_uint2(pack_h2(v.x - hx, v.y - hy), pack_h2(v.z - hz, v.w - hw));
}

// ---------------------------------- main -------------------------------------
__global__ void __launch_bounds__(THREADS, 1)
swin_attn_kernel(const float* __restrict__ patches,
                 const float* __restrict__ wq, const float* __restrict__ bq,
                 const float* __restrict__ wk, const float* __restrict__ bk,
                 const float* __restrict__ wv, const float* __restrict__ bvp,
                 const float* __restrict__ pos_bias,
                 const unsigned char* __restrict__ mask,
                 float* __restrict__ out) {
    extern __shared__ char smem[];
    float* bias_s = reinterpret_cast<float*>(smem + OFF_BIAS);
    const unsigned sbase = smem_u32(smem);

    const int tid  = threadIdx.x;
    const int w    = tid >> 5;
    const int lane = tid & 31;
    const int gid  = lane >> 2;
    const int tig  = lane & 3;
    const int bw2  = blockIdx.x * 2;
    const float NEG_INF = __int_as_float(0xff800000);

    // ---- stage A = X pair -> fp16 hi/lo, swizzled ----
    #pragma unroll
    for (int i = 0; i < 16; ++i) {
        int idx = tid + i * THREADS;
        int row = idx >> 6;
        int k0 = (idx & 63) * 4;
        const float* src = patches + (size_t)(bw2 + (row >> 6)) * (64 * Dc)
                           + (row & 63) * Dc + k0;
        float4 v = *reinterpret_cast<const float4*>(src);
        float hx = __half2float(__float2half_rn(v.x));
        float hy = __half2float(__float2half_rn(v.y));
        float hz = __half2float(__float2half_rn(v.z));
        float hw = __half2float(__float2half_rn(v.w));
        unsigned off = swz512(row, k0);
        *reinterpret_cast<uint2*>(smem + OFF_AHI + off) =
            make_uint2(pack_h2(v.x, v.y), pack_h2(v.z, v.w));
        *reinterpret_cast<uint2*>(smem + OFF_ALO + off) =
            make_uint2(pack_h2(v.x - hx, v.y - hy), pack_h2(v.z - hz, v.w - hw));
    }

    // ---- GEMM0 warp tiling + ldmatrix lane constants ----
    const int mg = w >> 2;
    const int ng = w & 3;
    unsigned abA[2]; int rotA[2];
    #pragma unroll
    for (int mt = 0; mt < 2; ++mt) {
        int r = 32 * mg + 16 * mt + (lane & 15);
        abA[mt] = (unsigned)(r * 512);
        rotA[mt] = ((lane >> 4) + r) & 31;
    }
    unsigned abW[3]; int rotW[3];
    #pragma unroll
    for (int nt = 0; nt < 3; ++nt) {
        int r = 24 * ng + 8 * nt + (lane & 7);
        abW[nt] = (unsigned)(r * 512);
        rotW[nt] = (((lane >> 3) & 1) + r) & 31;
    }

    // ---- attention warp tiling (GEMM1/GEMM2 share decomposition) ----
    const int winG = w >> 3;          // window 0/1
    const int w7   = w & 7;
    const int ms1  = w7 >> 1;         // m-stripe (16 q rows)
    const int nh1  = w7 & 1;          // n half
    const int nwG  = (bw2 + winG) & (NWc - 1);
    // fragment-mapped positional bias (head-invariant) -> 16 regs
    float bias_g1[2][4][2];
    #pragma unroll
    for (int rr = 0; rr < 2; ++rr)
        #pragma unroll
        for (int nt = 0; nt < 4; ++nt)
            #pragma unroll
            for (int cc = 0; cc < 2; ++cc) {
                int q = ms1 * 16 + gid + 8 * rr;
                int k = nh1 * 32 + nt * 8 + 2 * tig + cc;
                bias_g1[rr][nt][cc] =
                    pos_bias[((q >> 3) - (k >> 3) + 7) * 15 + ((q & 7) - (k & 7) + 7)];
            }
    // GEMM1 frag lane constants (Qs/Ks: 64B rows, 4 segs)
    const int rQ1 = winG * 64 + ms1 * 16 + (lane & 15);
    const unsigned aQ1 = (unsigned)(rQ1 * 64);
    const int rotQ1 = (lane >> 4) + rQ1;
    int rK1[4]; unsigned aK1[4]; int rotK1[4];
    #pragma unroll
    for (int nt = 0; nt < 4; ++nt) {
        rK1[nt] = winG * 64 + nh1 * 32 + nt * 8 + (lane & 7);
        aK1[nt] = (unsigned)(rK1[nt] * 64);
        rotK1[nt] = ((lane >> 3) & 1) + rK1[nt];
    }
    // GEMM2 frag lane constants (As 128 rows / Vt 64 rows: 128B rows, 8 segs)
    const int rA2 = winG * 64 + ms1 * 16 + (lane & 15);
    const unsigned aA2 = (unsigned)(rA2 * 128);
    const int rotA2 = (lane >> 4) + rA2;
    int rV2[2]; unsigned aV2[2]; int rotV2[2];
    #pragma unroll
    for (int nt = 0; nt < 2; ++nt) {
        rV2[nt] = winG * 32 + nh1 * 16 + nt * 8 + (lane & 7);
        aV2[nt] = (unsigned)(rV2[nt] * 128);
        rotV2[nt] = ((lane >> 3) & 1) + rV2[nt];
    }

    const unsigned AHIb = sbase + OFF_AHI, ALOb = sbase + OFF_ALO;
    const unsigned WHIb = sbase + OFF_WHI, WLOb = sbase + OFF_WLO;
    const unsigned QSHb = sbase + OFF_QSH, QSLb = sbase + OFF_QSL;
    const unsigned KSHb = sbase + OFF_KSH, KSLb = sbase + OFF_KSL;
    const unsigned ASHb = sbase + OFF_ASH, ASLb = sbase + OFF_ASL;
    const unsigned VTHb = sbase + OFF_VTH, VTLb = sbase + OFF_VTL;
    float* Lsf = reinterpret_cast<float*>(smem + OFF_LS);

    for (int h = 0; h < Hc; ++h) {
        __syncthreads();  // prior head GEMM2 reads of As/Vt done; A staged (h=0)

        // ---- stage W: copy from pre-swizzled globals ----
        {
            const uint4* sh = reinterpret_cast<const uint4*>(g_whi[h]);
            const uint4* sl = reinterpret_cast<const uint4*>(g_wlo[h]);
            uint4* dh = reinterpret_cast<uint4*>(smem + OFF_WHI);
            uint4* dl = reinterpret_cast<uint4*>(smem + OFF_WLO);
            #pragma unroll
            for (int i = 0; i < 6; ++i) {
                int j = tid + i * THREADS;
                dh[j] = sh[j];
                dl[j] = sl[j];
            }
        }
        if (tid < 96) {
            float b;
            if (tid < 32)      b = bq[h * 32 + tid];
            else if (tid < 64) b = bk[h * 32 + tid - 32];
            else               b = bvp[h * 32 + tid - 64];
            bias_s[tid] = b;
        }
        __syncthreads();

        // ---- GEMM0: D[128x96] = Xhi*Whi + Xhi*Wlo + Xlo*Whi, K=256 ----
        float acc[6][4];
        #pragma unroll
        for (int t = 0; t < 6; ++t)
            #pragma unroll
            for (int c = 0; c < 4; ++c) acc[t][c] = 0.f;

        #pragma unroll 4
        for (int st = 0; st < 16; ++st) {
            const int s2 = 2 * st;
            unsigned ah[2][4], al[2][4];
            #pragma unroll
            for (int mt = 0; mt < 2; ++mt) {
                unsigned off = abA[mt] + (((s2 + rotA[mt]) & 31) << 4);
                ldsm_x4(ah[mt], AHIb + off);
                ldsm_x4(al[mt], ALOb + off);
            }
            #pragma unroll
            for (int nt = 0; nt < 3; ++nt) {
                unsigned offw = abW[nt] + (((s2 + rotW[nt]) & 31) << 4);
                unsigned bh[2], bl[2];
                ldsm_x2(bh, WHIb + offw);
                ldsm_x2(bl, WLOb + offw);
                #pragma unroll
                for (int mt = 0; mt < 2; ++mt) {
                    mma16816(acc[mt * 3 + nt], ah[mt], bh);
                    mma16816(acc[mt * 3 + nt], ah[mt], bl);
                    mma16816(acc[mt * 3 + nt], al[mt], bh);
                }
            }
        }
        __syncthreads();  // W dead; union becomes Qs/Ks/Vt

        // ---- scatter: acc + bias -> Qs/Ks (fp16 hi/lo pairs) and Vt ----
        #pragma unroll
        for (int mt = 0; mt < 2; ++mt)
            #pragma unroll
            for (int nt0 = 0; nt0 < 3; ++nt0)
                #pragma unroll
                for (int rr = 0; rr < 2; ++rr) {
                    int R = 32 * mg + 16 * mt + 8 * rr + gid;   // stacked row 0..127
                    int C = 24 * ng + 8 * nt0 + 2 * tig;        // output col (even)
                    float v0 = acc[mt * 3 + nt0][rr * 2 + 0] + bias_s[C];
                    float v1 = acc[mt * 3 + nt0][rr * 2 + 1] + bias_s[C + 1];
                    if (C < 32) {
                        v0 *= QSCALE; v1 *= QSCALE;
                        __half h0 = __float2half_rn(v0), h1 = __float2half_rn(v1);
                        unsigned off = swz64(R, C);
                        *reinterpret_cast<unsigned*>(smem + OFF_QSH + off) =
                            pack_h2(v0, v1);
                        *reinterpret_cast<unsigned*>(smem + OFF_QSL + off) =
                            pack_h2(v0 - __half2float(h0), v1 - __half2float(h1));
                    } else if (C < 64) {
                        int d = C - 32;
                        __half h0 = __float2half_rn(v0), h1 = __float2half_rn(v1);
                        unsigned off = swz64(R, d);
                        *reinterpret_cast<unsigned*>(smem + OFF_KSH + off) =
                            pack_h2(v0, v1);
                        *reinterpret_cast<unsigned*>(smem + OFF_KSL + off) =
                            pack_h2(v0 - __half2float(h0), v1 - __half2float(h1));
                    } else {
                        int m = R & 63;
                        int vr0 = (R >> 6) * 32 + (C - 64);
                        __half h0 = __float2half_rn(v0);
                        __half h1 = __float2half_rn(v1);
                        unsigned o0 = swz128(vr0, m);
                        unsigned o1 = swz128(vr0 + 1, m);
                        *reinterpret_cast<__half*>(smem + OFF_VTH + o0) = h0;
                        *reinterpret_cast<__half*>(smem + OFF_VTL + o0) =
                            __float2half_rn(v0 - __half2float(h0));
                        *reinterpret_cast<__half*>(smem + OFF_VTH + o1) = h1;
                        *reinterpret_cast<__half*>(smem + OFF_VTL + o1) =
                            __float2half_rn(v1 - __half2float(h1));
                    }
                }
        __syncthreads();

        // ---- GEMM1: S = Q @ K^T (per window), k=32, 3-term split ----
        float s1[4][4];
        {
            #pragma unroll
            for (int t = 0; t < 4; ++t)
                #pragma unroll
                for (int c = 0; c < 4; ++c) s1[t][c] = 0.f;
            // prefetch mask u16s (hidden under mma)
            const unsigned char* mp1 = mask + ((size_t)(nwG * Hc + h) << 12);
            unsigned short mw[2][4];
            #pragma unroll
            for (int rr = 0; rr < 2; ++rr)
                #pragma unroll
                for (int nt = 0; nt < 4; ++nt) {
                    int q = ms1 * 16 + gid + 8 * rr;
                    int kb = nh1 * 32 + nt * 8 + 2 * tig;
                    mw[rr][nt] = *reinterpret_cast<const unsigned short*>(
                        mp1 + q * 64 + kb);
                }
            #pragma unroll
            for (int kst = 0; kst < 2; ++kst) {
                unsigned qh[4], ql[4];
                unsigned offq = aQ1 + (((2 * kst + rotQ1) & 3) << 4);
                ldsm_x4(qh, QSHb + offq);
                ldsm_x4(ql, QSLb + offq);
                #pragma unroll
                for (int nt = 0; nt < 4; ++nt) {
                    unsigned offk = aK1[nt] + (((2 * kst + rotK1[nt]) & 3) << 4);
                    unsigned kh[2], kl[2];
                    ldsm_x2(kh, KSHb + offk);
                    ldsm_x2(kl, KSLb + offk);
                    mma16816(s1[nt], qh, kh);
                    mma16816(s1[nt], qh, kl);
                    mma16816(s1[nt], ql, kh);
                }
            }
            __syncthreads();  // Qs/Ks dead; region becomes Ls
            #pragma unroll
            for (int nt = 0; nt < 4; ++nt)
                #pragma unroll
                for (int rr = 0; rr < 2; ++rr) {
                    int q_l = ms1 * 16 + gid + 8 * rr;
                    int row = winG * 64 + q_l;
                    int kb = nh1 * 32 + nt * 8 + 2 * tig;
                    float v0 = s1[nt][rr * 2 + 0] + bias_g1[rr][nt][0];
                    float v1 = s1[nt][rr * 2 + 1] + bias_g1[rr][nt][1];
                    unsigned short m16 = mw[rr][nt];
                    if (m16) {
                        if (m16 & 0x00ff) v0 = NEG_INF;
                        if (m16 & 0xff00) v1 = NEG_INF;
                    }
                    *reinterpret_cast<float2*>(Lsf + row * 68 + kb) =
                        make_float2(v0, v1);
                }
        }
        __syncthreads();

        // ---- log_softmax (rows 0..127 stacked), write As fp16 hi/lo ----
        {
            const int q = tid >> 2;       // stacked row
            const int r = tid & 3;
            const float* lp = Lsf + q * 68 + r * 16;
            float x[16];
            #pragma unroll
            for (int i = 0; i < 4; ++i) {
                float4 v = *reinterpret_cast<const float4*>(lp + i * 4);
                x[4 * i + 0] = v.x; x[4 * i + 1] = v.y;
                x[4 * i + 2] = v.z; x[4 * i + 3] = v.w;
            }
            float mx = x[0];
            #pragma unroll
            for (int i = 1; i < 16; ++i) mx = fmaxf(mx, x[i]);
            mx = fmaxf(mx, __shfl_xor_sync(0xffffffffu, mx, 1));
            mx = fmaxf(mx, __shfl_xor_sync(0xffffffffu, mx, 2));
            float ssum = 0.f;
            #pragma unroll
            for (int i = 0; i < 16; ++i) ssum += __expf(x[i] - mx);
            ssum += __shfl_xor_sync(0xffffffffu, ssum, 1);
            ssum += __shfl_xor_sync(0xffffffffu, ssum, 2);
            float lse = mx + __logf(ssum);
            __syncthreads();  // all Ls reads done; region becomes As
            #pragma unroll
            for (int i = 0; i < 8; ++i) {
                int key = r * 16 + 2 * i;
                float v0 = x[2 * i] - lse;
                float v1 = x[2 * i + 1] - lse;
                __half h0 = __float2half_rn(v0), h1 = __float2half_rn(v1);
                unsigned off = swz128(q, key);
                *reinterpret_cast<unsigned*>(smem + OFF_ASH + off) = pack_h2(v0, v1);
                *reinterpret_cast<unsigned*>(smem + OFF_ASL + off) =
                    pack_h2(v0 - __half2float(h0), v1 - __half2float(h1));
            }
        }
        __syncthreads();

        // ---- GEMM2: out = attn @ V (per window), k=64, 3-term split ----
        {
            float s2[2][4];
            #pragma unroll
            for (int t = 0; t < 2; ++t)
                #pragma unroll
                for (int c = 0; c < 4; ++c) s2[t][c] = 0.f;
            #pragma unroll
            for (int kst = 0; kst < 4; ++kst) {
                unsigned ah[4], al[4];
                unsigned offa = aA2 + (((2 * kst + rotA2) & 7) << 4);
                ldsm_x4(ah, ASHb + offa);
                ldsm_x4(al, ASLb + offa);
                #pragma unroll
                for (int nt = 0; nt < 2; ++nt) {
                    unsigned offv = aV2[nt] + (((2 * kst + rotV2[nt]) & 7) << 4);
                    unsigned vh[2], vl[2];
                    ldsm_x2(vh, VTHb + offv);
                    ldsm_x2(vl, VTLb + offv);
                    mma16816(s2[nt], ah, vh);
                    mma16816(s2[nt], ah, vl);
                    mma16816(s2[nt], al, vh);
                }
            }
            float* OgW = out + (size_t)(bw2 + winG) * (64 * Dc);
            #pragma unroll
            for (int nt = 0; nt < 2; ++nt)
                #pragma unroll
                for (int rr = 0; rr < 2; ++rr) {
                    int qrow = ms1 * 16 + gid + 8 * rr;
                    int col = h * 32 + nh1 * 16 + nt * 8 + 2 * tig;
                    *reinterpret_cast<float2*>(OgW + qrow * Dc + col) =
                        make_float2(s2[nt][rr * 2], s2[nt][rr * 2 + 1]);
                }
        }
        // head-loop top sync orders As/Vt reads before next W staging
    }
}

extern "C" void kernel_launch(void* const* d_in, const int* in_sizes, int n_in,
                              void* d_out, int out_size) {
    (void)in_sizes; (void)n_in; (void)out_size;
    const float* patches = (const float*)d_in[0];
    const float* wq = (const float*)d_in[1];
    const float* bq = (const float*)d_in[2];
    const float* wk = (const float*)d_in[3];
    const float* bk = (const float*)d_in[4];
    const float* wv = (const float*)d_in[5];
    const float* bv = (const float*)d_in[6];
    const float* pos = (const float*)d_in[7];
    const unsigned char* mask = (const unsigned char*)d_in[8];
    float* out = (float*)d_out;

    prep_w_kernel<<<96, 512>>>(wq, wk, wv);

    cudaFuncSetAttribute(swin_attn_kernel,
                         cudaFuncAttributeMaxDynamicSharedMemorySize, SMEM_BYTES);
    swin_attn_kernel<<<2048, THREADS, SMEM_BYTES>>>(
        patches, wq, bq, wk, bk, wv, bv, pos, mask, out);
}